// round 15
// baseline (speedup 1.0000x reference)
#include <cuda_runtime.h>
#include <cuda_bf16.h>

#define NQ    18
#define NBAT  16
#define NTHR  (NQ * NBAT)   // 288: one thread per (batch, site)

// Sum/difference-basis MPS, forward sweep only (derivation verified R2..R13).
// Site map (constant products folded on the producer side):
//   sd' = z3*dd ; dd' = wx*p + w*sd ; p' = e*p + ey*sd
//   z_i = sd_i + q01_i * p_i ,  q01_i = 2*s0_{i+1}  (2.0 terminator at i=17)
// with z3=c1*c0, w=c1, wx=c1*2s0, ey=-s1*0.5s0, e=-s1  (FULL angles).
// R14 deltas vs R13 (shell otherwise identical): carried float2 coefficient
// read (2 LDS/site instead of 3) and register-accumulated outputs stored as
// 9x STG.64 after the loop (instead of 18x STG.32 inside it).

__shared__ float4 g_cA[NQ][NBAT];        // {z3, w, wx, ey}
__shared__ float2 g_cB[NQ + 1][NBAT];    // {e_s, 2*s0_s}; slot NQ = {0, 2.0}

__global__ void __launch_bounds__(NTHR, 1)
quantum_mps_kernel(const float* __restrict__ in, float* __restrict__ out) {
    const int tid = threadIdx.x;

    // ---- phase 1: one (batch, site) per thread: 2 loads, 2 sincosf, pack
    {
        const int b = tid / NQ, s = tid % NQ;
        float s0, c0, s1, c1;
        __sincosf(in[b * 36 + s],      &s0, &c0);   // layer 0
        __sincosf(in[b * 36 + 18 + s], &s1, &c1);   // layer 1
        g_cA[s][b] = make_float4(c1 * c0, c1, c1 * (s0 + s0), -s1 * 0.5f * s0);
        g_cB[s][b] = make_float2(-s1, s0 + s0);
        if (s == 0) g_cB[NQ][b] = make_float2(0.0f, 2.0f);   // terminator (thread-local per b)
    }
    __syncthreads();

    // ---- phase 2: forward sweep, warp 0 (16 lanes); outputs in registers
    if (tid < NBAT) {
        const int b = tid;
        float sd = 1.0f, dd = 1.0f, p = 0.0f;
        float e = g_cB[0][b].x;              // e_0 (carried)
        float z[NQ];
        #pragma unroll
        for (int t = 0; t < NQ; t++) {
            const float4 a   = g_cA[t][b];       // {z3, w, wx, ey}
            const float2 cbn = g_cB[t + 1][b];   // {e_{t+1}, q01_t}
            const float nsd = a.x * dd;
            const float ndd = fmaf(a.z, p, a.y * sd);
            const float np  = fmaf(e,   p, a.w * sd);
            sd = nsd; dd = ndd; p = np;
            z[t] = fmaf(cbn.y, np, nsd);
            e = cbn.x;
        }
        // 18 contiguous floats per batch -> 9x STG.64 (8-byte aligned: 72*b)
        float2* o2 = reinterpret_cast<float2*>(out + b * NQ);
        #pragma unroll
        for (int j = 0; j < NQ / 2; j++)
            o2[j] = make_float2(z[2 * j], z[2 * j + 1]);
    }
}

extern "C" void kernel_launch(void* const* d_in, const int* in_sizes, int n_in,
                              void* d_out, int out_size) {
    const float* in  = (const float*)d_in[0];
    float*       out = (float*)d_out;
    quantum_mps_kernel<<<1, NTHR>>>(in, out);
}

// round 16
// speedup vs baseline: 1.3586x; 1.3586x over previous
#include <cuda_runtime.h>
#include <cuda_bf16.h>

#define NQ    18
#define NBAT  16
#define NTHR  (NQ * NBAT)   // 288: one thread per (batch, site)

// Sum/difference-basis MPS, forward sweep only (derivation verified R2..R14).
// Site map (constant products folded on the producer side):
//   sd' = z3*dd ; dd' = wx*p + w*sd ; p' = e*p + ey*sd
//   z_i = sd_i + q01_i * p_i ,  q01_i = 2*s0_{i+1}  (2.0 terminator at i=17)
// with z3=c1*c0, w=c1, wx=c1*2s0, ey=-s1*0.5s0, e=-s1  (FULL angles).
// R15 delta vs R13 (best dur, 4.64us): producer warps signal via bar.arrive
// and retire; only the sweep warp blocks on bar.sync (producer-consumer named
// barrier instead of monolithic __syncthreads). Phase-2 body unchanged.

__shared__ float4 g_cA[NQ][NBAT];   // {z3, w, wx, ey}
__shared__ float2 g_cB[NQ][NBAT];   // {e, 2*s0}   (all writes thread-local)

__global__ void __launch_bounds__(NTHR, 1)
quantum_mps_kernel(const float* __restrict__ in, float* __restrict__ out) {
    const int tid = threadIdx.x;

    // ---- phase 1: one (batch, site) per thread: 2 loads, 2 sincosf, pack
    {
        const int b = tid / NQ, s = tid % NQ;
        float s0, c0, s1, c1;
        __sincosf(in[b * 36 + s],      &s0, &c0);   // layer 0
        __sincosf(in[b * 36 + 18 + s], &s1, &c1);   // layer 1
        g_cA[s][b] = make_float4(c1 * c0, c1, c1 * (s0 + s0), -s1 * 0.5f * s0);
        g_cB[s][b] = make_float2(-s1, s0 + s0);
    }

    // ---- producer-consumer barrier: warps 1..8 arrive (no wait) and retire;
    //      the sweep warp blocks until all 288 threads have arrived.
    if (tid >= 32) {
        asm volatile("bar.arrive 0, %0;" :: "r"(NTHR) : "memory");
        return;
    }
    asm volatile("bar.sync 0, %0;" :: "r"(NTHR) : "memory");

    // ---- phase 2: forward sweep + in-loop readout, warp 0 (16 lanes)
    if (tid < NBAT) {
        const int b = tid;
        float sd = 1.0f, dd = 1.0f, p = 0.0f;
        #pragma unroll
        for (int t = 0; t < NQ; t++) {
            const float4 a  = g_cA[t][b];   // {z3, w, wx, ey}
            const float  e  = g_cB[t][b].x;
            const float nsd = a.x * dd;
            const float ndd = fmaf(a.z, p, a.y * sd);
            const float np  = fmaf(e,   p, a.w * sd);
            sd = nsd; dd = ndd; p = np;
            // q01 = 2*s0 of site t+1 (thread-local read; unrolled -> compile-time)
            const float q01 = (t < NQ - 1) ? g_cB[t + 1][b].y : 2.0f;
            out[b * NQ + t] = fmaf(q01, p, sd);
        }
    }
}

extern "C" void kernel_launch(void* const* d_in, const int* in_sizes, int n_in,
                              void* d_out, int out_size) {
    const float* in  = (const float*)d_in[0];
    float*       out = (float*)d_out;
    quantum_mps_kernel<<<1, NTHR>>>(in, out);
}

// round 17
// speedup vs baseline: 1.3873x; 1.0211x over previous
#include <cuda_runtime.h>
#include <cuda_bf16.h>

#define NQ    18
#define NBAT  16
#define NTHR  (NQ * NBAT)   // 288: one thread per (batch, site)

// Sum/difference-basis MPS, forward sweep only (derivation verified R2..R15).
// Site map (constant products folded on the producer side):
//   sd' = z3*dd ; dd' = wx*p + w*sd ; p' = e*p + ey*sd
//   z_i = sd_i + q01_i * p_i ,  q01_i = 2*s0_{i+1}  (2.0 terminator at i=17)
// with z3=c1*c0, w=c1, wx=c1*2s0, ey=-s1*0.5s0, e=-s1  (FULL angles).
// R16 = R13/R15 winning shell (1-D 288 block, warp-0 sweep, in-loop STG,
// arrive/sync barrier split) + R14's carried-coefficient read (2 LDS/site).

__shared__ float4 g_cA[NQ][NBAT];        // {z3, w, wx, ey}
__shared__ float2 g_cB[NQ + 1][NBAT];    // {e_s, 2*s0_s}; slot NQ = {0, 2.0}

__global__ void __launch_bounds__(NTHR, 1)
quantum_mps_kernel(const float* __restrict__ in, float* __restrict__ out) {
    const int tid = threadIdx.x;

    // ---- phase 1: one (batch, site) per thread: 2 loads, 2 sincosf, pack
    {
        const int b = tid / NQ, s = tid % NQ;
        float s0, c0, s1, c1;
        __sincosf(in[b * 36 + s],      &s0, &c0);   // layer 0
        __sincosf(in[b * 36 + 18 + s], &s1, &c1);   // layer 1
        g_cA[s][b] = make_float4(c1 * c0, c1, c1 * (s0 + s0), -s1 * 0.5f * s0);
        g_cB[s][b] = make_float2(-s1, s0 + s0);
        if (s == 0) g_cB[NQ][b] = make_float2(0.0f, 2.0f);   // terminator (thread-local per b)
    }

    // ---- producer-consumer barrier: warps 1..8 signal and retire;
    //      only the sweep warp blocks until all 288 have arrived.
    if (tid >= 32) {
        asm volatile("bar.arrive 0, %0;" :: "r"(NTHR) : "memory");
        return;
    }
    asm volatile("bar.sync 0, %0;" :: "r"(NTHR) : "memory");

    // ---- phase 2: forward sweep + in-loop readout, warp 0 (16 lanes)
    if (tid < NBAT) {
        const int b = tid;
        float sd = 1.0f, dd = 1.0f, p = 0.0f;
        float e = g_cB[0][b].x;                  // e_0 (carried)
        #pragma unroll
        for (int t = 0; t < NQ; t++) {
            const float4 a   = g_cA[t][b];       // {z3, w, wx, ey}
            const float2 cbn = g_cB[t + 1][b];   // {e_{t+1}, q01_t}
            const float nsd = a.x * dd;
            const float ndd = fmaf(a.z, p, a.y * sd);
            const float np  = fmaf(e,   p, a.w * sd);
            sd = nsd; dd = ndd; p = np;
            out[b * NQ + t] = fmaf(cbn.y, np, nsd);   // z_t, off the update chain
            e = cbn.x;
        }
    }
}

extern "C" void kernel_launch(void* const* d_in, const int* in_sizes, int n_in,
                              void* d_out, int out_size) {
    const float* in  = (const float*)d_in[0];
    float*       out = (float*)d_out;
    quantum_mps_kernel<<<1, NTHR>>>(in, out);
}